// round 1
// baseline (speedup 1.0000x reference)
#include <cuda_runtime.h>
#include <cuda_bf16.h>
#include <cstdint>

// Problem shape (fixed by reference setup_inputs)
#define B_  16
#define C_  384
#define CR_ 96
#define HW_ 12544      // 112*112
#define HW4_ 3136      // HW/4, float4 count per plane
#define NPLANES_ (B_ * C_)   // 6144

// Scratch (no cudaMalloc allowed) — device globals.
__device__ float g_mean[NPLANES_];
__device__ float g_scale[NPLANES_];

// ---------------------------------------------------------------------------
// Kernel 1: per-(b,c)-plane mean over H*W. One CTA per plane, float4 loads.
// ---------------------------------------------------------------------------
__global__ void __launch_bounds__(256) se_reduce_kernel(const float* __restrict__ x) {
    const int plane = blockIdx.x;                    // b*C + c
    const float4* __restrict__ p =
        reinterpret_cast<const float4*>(x + (size_t)plane * HW_);

    float sum = 0.0f;
    // 3136 float4 / 256 threads = 12.25 iters; grid-stride within plane.
    #pragma unroll 4
    for (int i = threadIdx.x; i < HW4_; i += 256) {
        float4 v = p[i];
        sum += (v.x + v.y) + (v.z + v.w);
    }

    // warp reduce
    #pragma unroll
    for (int o = 16; o > 0; o >>= 1)
        sum += __shfl_down_sync(0xffffffffu, sum, o);

    __shared__ float sdata[8];
    const int lane = threadIdx.x & 31;
    const int wid  = threadIdx.x >> 5;
    if (lane == 0) sdata[wid] = sum;
    __syncthreads();
    if (wid == 0) {
        sum = (lane < 8) ? sdata[lane] : 0.0f;
        #pragma unroll
        for (int o = 4; o > 0; o >>= 1)
            sum += __shfl_down_sync(0xffffffffu, sum, o);
        if (lane == 0) g_mean[plane] = sum * (1.0f / (float)HW_);
    }
}

// ---------------------------------------------------------------------------
// Kernel 2: tiny FC chain per batch. 16 CTAs x 384 threads. Negligible cost.
//   t = relu(W1 @ s + b1)   [96]
//   o = hardsigmoid(W2 @ t + b2)  [384]
// ---------------------------------------------------------------------------
__global__ void __launch_bounds__(C_) se_fc_kernel(const float* __restrict__ w1,
                                                   const float* __restrict__ b1,
                                                   const float* __restrict__ w2,
                                                   const float* __restrict__ b2) {
    const int b   = blockIdx.x;
    const int tid = threadIdx.x;

    __shared__ float s[C_];
    __shared__ float t[CR_];

    s[tid] = g_mean[b * C_ + tid];
    __syncthreads();

    if (tid < CR_) {
        float acc = b1[tid];
        const float* __restrict__ wr = w1 + tid * C_;   // w1[r, c]
        #pragma unroll 8
        for (int c = 0; c < C_; c++) acc = fmaf(s[c], wr[c], acc);
        t[tid] = fmaxf(acc, 0.0f);
    }
    __syncthreads();

    float acc = b2[tid];
    const float* __restrict__ wc = w2 + tid * CR_;      // w2[c, r]
    #pragma unroll 8
    for (int r = 0; r < CR_; r++) acc = fmaf(t[r], wc[r], acc);

    // hardsigmoid: clip(x/6 + 0.5, 0, 1) == saturate
    g_scale[b * C_ + tid] = __saturatef(fmaf(acc, 1.0f / 6.0f, 0.5f));
}

// ---------------------------------------------------------------------------
// Kernel 3: broadcast multiply. One CTA per plane, float4 streaming.
// ---------------------------------------------------------------------------
__global__ void __launch_bounds__(256) se_scale_kernel(const float* __restrict__ x,
                                                       float* __restrict__ out) {
    const int plane = blockIdx.x;
    const float sc = g_scale[plane];
    const float4* __restrict__ p =
        reinterpret_cast<const float4*>(x + (size_t)plane * HW_);
    float4* __restrict__ o = reinterpret_cast<float4*>(out + (size_t)plane * HW_);

    #pragma unroll 4
    for (int i = threadIdx.x; i < HW4_; i += 256) {
        float4 v = p[i];
        v.x *= sc; v.y *= sc; v.z *= sc; v.w *= sc;
        o[i] = v;
    }
}

// ---------------------------------------------------------------------------
extern "C" void kernel_launch(void* const* d_in, const int* in_sizes, int n_in,
                              void* d_out, int out_size) {
    const float* x  = (const float*)d_in[0];
    const float* w1 = (const float*)d_in[1];
    const float* b1 = (const float*)d_in[2];
    const float* w2 = (const float*)d_in[3];
    const float* b2 = (const float*)d_in[4];
    float* out = (float*)d_out;

    se_reduce_kernel<<<NPLANES_, 256>>>(x);
    se_fc_kernel<<<B_, C_>>>(w1, b1, w2, b2);
    se_scale_kernel<<<NPLANES_, 256>>>(x, out);
}

// round 2
// speedup vs baseline: 1.0466x; 1.0466x over previous
#include <cuda_runtime.h>
#include <cuda_bf16.h>
#include <cstdint>

// Problem shape (fixed by reference setup_inputs)
#define B_  16
#define C_  384
#define CR_ 96
#define HW_ 12544          // 112*112
#define HW4_ 3136          // HW/4, float4 count per plane
#define NPLANES_ (B_ * C_) // 6144

#define RTHREADS_ 448      // 3136 / 448 == 7 exactly
#define RITERS_   7

// Scratch (no cudaMalloc allowed) — device globals.
__device__ float g_mean[NPLANES_];
__device__ float g_scale[NPLANES_];

// ---------------------------------------------------------------------------
// Kernel 1: per-(b,c)-plane mean. One CTA per plane, 448 thr x 7 float4 exact.
// Default (allocating) loads so the tail of x stays resident in L2 for reuse
// by the scale kernel.
// ---------------------------------------------------------------------------
__global__ void __launch_bounds__(RTHREADS_) se_reduce_kernel(const float* __restrict__ x) {
    const int plane = blockIdx.x;
    const float4* __restrict__ p =
        reinterpret_cast<const float4*>(x + (size_t)plane * HW_);

    // Front-batch all 7 loads (MLP=7), then sum.
    float4 v[RITERS_];
    #pragma unroll
    for (int k = 0; k < RITERS_; k++)
        v[k] = p[threadIdx.x + k * RTHREADS_];

    float sum = 0.0f;
    #pragma unroll
    for (int k = 0; k < RITERS_; k++)
        sum += (v[k].x + v[k].y) + (v[k].z + v[k].w);

    // warp reduce
    #pragma unroll
    for (int o = 16; o > 0; o >>= 1)
        sum += __shfl_down_sync(0xffffffffu, sum, o);

    __shared__ float sdata[RTHREADS_ / 32];   // 14 warps
    const int lane = threadIdx.x & 31;
    const int wid  = threadIdx.x >> 5;
    if (lane == 0) sdata[wid] = sum;
    __syncthreads();
    if (wid == 0) {
        sum = (lane < (RTHREADS_ / 32)) ? sdata[lane] : 0.0f;
        #pragma unroll
        for (int o = 8; o > 0; o >>= 1)
            sum += __shfl_down_sync(0xffffffffu, sum, o);
        if (lane == 0) g_mean[plane] = sum * (1.0f / (float)HW_);
    }
}

// ---------------------------------------------------------------------------
// Kernel 2: tiny FC chain per batch. 16 CTAs x 384 threads. Negligible cost.
// ---------------------------------------------------------------------------
__global__ void __launch_bounds__(C_) se_fc_kernel(const float* __restrict__ w1,
                                                   const float* __restrict__ b1,
                                                   const float* __restrict__ w2,
                                                   const float* __restrict__ b2) {
    const int b   = blockIdx.x;
    const int tid = threadIdx.x;

    __shared__ float s[C_];
    __shared__ float t[CR_];

    s[tid] = g_mean[b * C_ + tid];
    __syncthreads();

    if (tid < CR_) {
        float acc = b1[tid];
        const float* __restrict__ wr = w1 + tid * C_;   // w1[r, c]
        #pragma unroll 8
        for (int c = 0; c < C_; c++) acc = fmaf(s[c], wr[c], acc);
        t[tid] = fmaxf(acc, 0.0f);
    }
    __syncthreads();

    float acc = b2[tid];
    const float* __restrict__ wc = w2 + tid * CR_;      // w2[c, r]
    #pragma unroll 8
    for (int r = 0; r < CR_; r++) acc = fmaf(t[r], wc[r], acc);

    // hardsigmoid: clip(x/6 + 0.5, 0, 1) == saturate
    g_scale[b * C_ + tid] = __saturatef(fmaf(acc, 1.0f / 6.0f, 0.5f));
}

// ---------------------------------------------------------------------------
// Kernel 3: broadcast multiply. REVERSE plane order so the first wave reads
// the x-tail that the reduce kernel left in L2 (~126MB reuse window).
// Streaming hints (.cs) because nothing read/written here is reused.
// ---------------------------------------------------------------------------
__global__ void __launch_bounds__(RTHREADS_) se_scale_kernel(const float* __restrict__ x,
                                                             float* __restrict__ out) {
    const int plane = (NPLANES_ - 1) - blockIdx.x;
    const float sc = g_scale[plane];
    const float4* __restrict__ p =
        reinterpret_cast<const float4*>(x + (size_t)plane * HW_);
    float4* __restrict__ o = reinterpret_cast<float4*>(out + (size_t)plane * HW_);

    // Front-batch 7 loads, then 7 streaming stores.
    float4 v[RITERS_];
    #pragma unroll
    for (int k = 0; k < RITERS_; k++)
        v[k] = __ldcs(&p[threadIdx.x + k * RTHREADS_]);

    #pragma unroll
    for (int k = 0; k < RITERS_; k++) {
        v[k].x *= sc; v[k].y *= sc; v[k].z *= sc; v[k].w *= sc;
        __stcs(&o[threadIdx.x + k * RTHREADS_], v[k]);
    }
}

// ---------------------------------------------------------------------------
extern "C" void kernel_launch(void* const* d_in, const int* in_sizes, int n_in,
                              void* d_out, int out_size) {
    const float* x  = (const float*)d_in[0];
    const float* w1 = (const float*)d_in[1];
    const float* b1 = (const float*)d_in[2];
    const float* w2 = (const float*)d_in[3];
    const float* b2 = (const float*)d_in[4];
    float* out = (float*)d_out;

    se_reduce_kernel<<<NPLANES_, RTHREADS_>>>(x);
    se_fc_kernel<<<B_, C_>>>(w1, b1, w2, b2);
    se_scale_kernel<<<NPLANES_, RTHREADS_>>>(x, out);
}